// round 8
// baseline (speedup 1.0000x reference)
#include <cuda_runtime.h>
#include <cuda_fp16.h>
#include <cstdint>

// ---------------- problem constants ----------------
#define BB   2
#define L2C  1024
#define L1C  8192
#define L0C  65536
#define SC   (L2C + L1C + L0C)   // 74752
#define DC   256

// ---------------- scratch (__device__ globals) ----------------
__device__ __half g_Ehi[(long)BB * SC * DC];
__device__ __half g_Elo[(long)BB * SC * DC];
__device__ __half g_W0[256 * 2048];
__device__ __half g_W1[256 * 2048];
__device__ __half g_W2[256 * 1024];
__device__ __half g_y0hi[(long)BB * L1C * DC], g_y0lo[(long)BB * L1C * DC];
__device__ __half g_x1hi[BB * L1C * DC], g_x1lo[BB * L1C * DC];
__device__ __half g_y1hi[BB * 1024 * DC], g_y1lo[BB * 1024 * DC];
__device__ __half g_x2hi[BB * L2C * DC], g_x2lo[BB * L2C * DC];
__device__ int g_srcrow1[BB * L1C];
__device__ int g_srcrow2[BB * L2C];
__device__ int g_outdst[BB * 256];

// ---------------- helpers ----------------
__device__ __forceinline__ uint32_t smem_u32(const void* p) {
    uint32_t a;
    asm("{ .reg .u64 t; cvta.to.shared.u64 t, %1; cvt.u32.u64 %0, t; }" : "=r"(a) : "l"(p));
    return a;
}

__device__ __forceinline__ void split2h(float x, __half& h, __half& l) {
    h = __float2half(x);
    l = __float2half(x - __half2float(h));
}

__device__ __forceinline__ void cpasync16(uint32_t saddr, const void* gaddr) {
    asm volatile("cp.async.cg.shared.global [%0], [%1], 16;" :: "r"(saddr), "l"(gaddr));
}

__device__ __forceinline__ void ldsm4(uint32_t* r, uint32_t a) {
    asm volatile("ldmatrix.sync.aligned.m8n8.x4.shared.b16 {%0,%1,%2,%3}, [%4];"
                 : "=r"(r[0]), "=r"(r[1]), "=r"(r[2]), "=r"(r[3]) : "r"(a));
}

__device__ __forceinline__ void mma16816(float* d, const uint32_t* a, const uint32_t* b) {
    asm volatile(
        "mma.sync.aligned.m16n8k16.row.col.f32.f16.f16.f32 "
        "{%0,%1,%2,%3}, {%4,%5,%6,%7}, {%8,%9}, {%0,%1,%2,%3};"
        : "+f"(d[0]), "+f"(d[1]), "+f"(d[2]), "+f"(d[3])
        : "r"(a[0]), "r"(a[1]), "r"(a[2]), "r"(a[3]), "r"(b[0]), "r"(b[1]));
}

// ---------------- warp-shuffle exclusive scan over 1024 threads ----------------
__device__ __forceinline__ int exscan1024(int v, int tid, int* sW, int* total) {
    int lane = tid & 31, w = tid >> 5;
    int x = v;
    #pragma unroll
    for (int o = 1; o < 32; o <<= 1) {
        int t = __shfl_up_sync(0xFFFFFFFFu, x, o);
        if (lane >= o) x += t;
    }
    if (lane == 31) sW[w] = x;
    __syncthreads();
    if (tid < 32) {
        int y = sW[lane];
        #pragma unroll
        for (int o = 1; o < 32; o <<= 1) {
            int t = __shfl_up_sync(0xFFFFFFFFu, y, o);
            if (lane >= o) y += t;
        }
        sW[lane] = y;
    }
    __syncthreads();
    int off = (w == 0) ? 0 : sW[w - 1];
    int tot = sW[31];
    __syncthreads();
    *total = tot;
    return off + x - v;
}

// ---------------- mega prep kernel: indices | wsplit | zero-out | embed ----------------
#define IDX_B0    0
#define WSP_B0    6
#define WSP_NB    1280          // 1310720 / 1024
#define ZER_B0    (WSP_B0 + WSP_NB)           // 1286
#define ZER_NB    8
#define EMB_B0    (ZER_B0 + ZER_NB)           // 1294
#define EMB_NB    ((BB * SC + 7) / 8)         // 18688
#define PREP_GRID (EMB_B0 + EMB_NB)

__global__ void __launch_bounds__(1024) k_prep(
    const int* __restrict__ value, const int* __restrict__ depth,
    const int* __restrict__ position,
    const float* __restrict__ emb_val, const float* __restrict__ emb_dep,
    const float* __restrict__ emb_pos,
    const float* __restrict__ W0, const float* __restrict__ W1,
    const float* __restrict__ W2, float* __restrict__ out)
{
    __shared__ int sOrder[8192];
    __shared__ int sScan[32];
    int bid = blockIdx.x, tid = threadIdx.x;

    if (bid >= EMB_B0) {
        // ---- embedding -> hi/lo fp16 ----
        long r = (long)(bid - EMB_B0) * 8 + (tid >> 7);
        if (r >= (long)BB * SC) return;
        int d = (tid & 127) * 2;
        int v = value[r], dep = depth[r];
        const int* p = position + r * 3;
        float2 e = *(const float2*)&emb_val[v * DC + d];
        float2 t;
        t = *(const float2*)&emb_dep[dep * DC + d];             e.x += t.x; e.y += t.y;
        t = *(const float2*)&emb_pos[(0 * 33 + p[0]) * DC + d]; e.x += t.x; e.y += t.y;
        t = *(const float2*)&emb_pos[(1 * 33 + p[1]) * DC + d]; e.x += t.x; e.y += t.y;
        t = *(const float2*)&emb_pos[(2 * 33 + p[2]) * DC + d]; e.x += t.x; e.y += t.y;
        __half h0, l0, h1, l1;
        split2h(e.x, h0, l0); split2h(e.y, h1, l1);
        *(__half2*)&g_Ehi[r * DC + d] = __halves2half2(h0, h1);
        *(__half2*)&g_Elo[r * DC + d] = __halves2half2(l0, l1);
        return;
    }
    if (bid >= ZER_B0) {
        // ---- zero output buffer (2*256*256 floats = 32768 float4) ----
        float4 z = make_float4(0.f, 0.f, 0.f, 0.f);
        for (int i = (bid - ZER_B0) * 1024 + tid; i < 32768; i += ZER_NB * 1024)
            ((float4*)out)[i] = z;
        return;
    }
    if (bid >= WSP_B0) {
        // ---- weight convert ----
        int idx = (bid - WSP_B0) * 1024 + tid;
        const float* W; __half* O; int sK;
        if (idx < 524288)        { W = W0; O = g_W0; sK = 8; }
        else if (idx < 1048576)  { idx -= 524288;  W = W1; O = g_W1; sK = 8; }
        else if (idx < 1310720)  { idx -= 1048576; W = W2; O = g_W2; sK = 4; }
        else return;
        int d = idx & 255;
        int rem = idx >> 8;
        int t = rem % sK;
        int o = rem / sK;
        O[o * (sK * 256) + t * 256 + d] = __float2half(W[(o * 256 + d) * sK + t]);
        return;
    }

    // ---- index precomputation: 6 blocks (b, sec) ----
    int b = bid >> 1;            // bid 0..5 -> b = bid/3? careful: use b = bid/3
    b = bid / 3;
    int sec = bid % 3;
    const int* vb = value + (long)b * SC;

    if (sec == 0) {
        int base = tid * 8, local = 0;
        unsigned mask = 0;
        #pragma unroll
        for (int i = 0; i < 8; i++) {
            int p = (vb[L2C + L1C + (base + i) * 8] != 0);
            mask |= (unsigned)p << i; local += p;
        }
        int tot; int ex = exscan1024(local, tid, sScan, &tot);
        int rt = ex, rf = base - ex;
        #pragma unroll
        for (int i = 0; i < 8; i++) {
            int j = base + i;
            if ((mask >> i) & 1u) sOrder[rt++] = j;
            else                  sOrder[tot + rf++] = j;
        }
        __syncthreads();
        local = 0; mask = 0;
        #pragma unroll
        for (int i = 0; i < 8; i++) {
            int p = (vb[L2C + base + i] == 2);
            mask |= (unsigned)p << i; local += p;
        }
        ex = exscan1024(local, tid, sScan, &tot);
        int r = ex;
        #pragma unroll
        for (int i = 0; i < 8; i++) {
            int j = base + i; int sr = -1;
            if ((mask >> i) & 1u) { sr = sOrder[min(r, 8191)]; r++; }
            g_srcrow1[b * L1C + j] = sr;
        }
    } else if (sec == 1) {
        int p = (vb[L2C + tid * 8] != 0);
        int tot; int ex = exscan1024(p, tid, sScan, &tot);
        if (p) sOrder[ex] = tid;
        else   sOrder[tot + tid - ex] = tid;
        __syncthreads();
        int q = (vb[tid] == 2);
        int ex2 = exscan1024(q, tid, sScan, &tot);
        g_srcrow2[b * L2C + tid] = q ? sOrder[min(ex2, 1023)] : -1;
    } else {
        int any = 0;
        #pragma unroll
        for (int t = 0; t < 8; t++) any |= (vb[L2C + tid * 8 + t] == 2);
        sOrder[tid] = any;
        __syncthreads();
        int p = (vb[tid] == 2);
        int tot; int ex = exscan1024(p, tid, sScan, &tot);
        int m2 = p ? sOrder[min(ex, 1023)] : 0;
        sOrder[2048 + tid] = m2;
        __syncthreads();
        int m2g = 0;
        if (tid < 256)
            m2g = sOrder[2048 + 4 * tid] | sOrder[2048 + 4 * tid + 1]
                | sOrder[2048 + 4 * tid + 2] | sOrder[2048 + 4 * tid + 3];
        int tot2; int ex2 = exscan1024((tid < 256 && m2g) ? 1 : 0, tid, sScan, &tot2);
        if (tid < 256) g_outdst[b * 256 + tid] = m2g ? ex2 : -1;   // src -> dest slot
    }
}

// ---------------- 2-term fp16 split GEMM via mma.sync ----------------
// OUTM=1: write hi/lo fp16 pair; OUTM=2: fp32 scatter rows via rowmap into out.
template <int BM, int BN, int KK, int STAGES, int OUTM>
__global__ void __launch_bounds__(256, 2) k_gemm(
    const __half* __restrict__ Ahi, const __half* __restrict__ Alo, long strideA,
    const __half* __restrict__ Bh, const float* __restrict__ bias,
    __half* __restrict__ Chi, __half* __restrict__ Clo,
    float* __restrict__ Cf, const int* __restrict__ rowmap, long strideC)
{
    constexpr int NC = KK / 64;
    constexpr int P = STAGES - 1;
    constexpr int ABYTES = BM * 128;
    constexpr int BBYTES = BN * 128;
    constexpr int STAGE = 2 * ABYTES + BBYTES;
    constexpr int WM = BM / 2, WN = BN / 4;
    constexpr int MT = WM / 16, NP = WN / 16;
    constexpr int TOTROWS = 2 * BM + BN;

    extern __shared__ __align__(1024) char smem[];
    uint32_t sb = smem_u32(smem);

    int tid = threadIdx.x;
    int lane = tid & 31, wid = tid >> 5;
    int wm0 = (wid >> 2) * WM;
    int wn0 = (wid & 3) * WN;
    int m0 = blockIdx.x * BM;
    int n0 = blockIdx.y * BN;
    int b = blockIdx.z;

    const __half* Ah = Ahi + (long)b * strideA;
    const __half* Al = Alo + (long)b * strideA;

    float acc[MT][2 * NP][4];
    #pragma unroll
    for (int i = 0; i < MT; i++)
        #pragma unroll
        for (int j = 0; j < 2 * NP; j++)
            #pragma unroll
            for (int k = 0; k < 4; k++) acc[i][j][k] = 0.f;

    auto load_chunk = [&](int c) {
        uint32_t st = sb + (uint32_t)((c % STAGES) * STAGE);
        long k0 = (long)c * 64;
        #pragma unroll
        for (int i = tid; i < TOTROWS * 8; i += 256) {
            int r = i >> 3, seg = i & 7;
            const __half* g;
            uint32_t base;
            if (r < BM)          { g = Ah + (long)(m0 + r) * KK;                  base = st; }
            else if (r < 2 * BM) { int rr = r - BM;     g = Al + (long)(m0 + rr) * KK; base = st + ABYTES;     r = rr; }
            else                 { int rr = r - 2 * BM; g = Bh + (long)(n0 + rr) * KK; base = st + 2 * ABYTES; r = rr; }
            uint32_t off = (uint32_t)(r * 128 + seg * 16);
            uint32_t dst = base + (off ^ (uint32_t)((r & 7) << 4));
            cpasync16(dst, g + k0 + seg * 8);
        }
        asm volatile("cp.async.commit_group;" ::: "memory");
    };

    #pragma unroll
    for (int pc = 0; pc < P && pc < NC; pc++) load_chunk(pc);

    const uint32_t xorm = (uint32_t)((lane & 7) << 4);
    const uint32_t a_lrow = (uint32_t)(lane & 15);
    const uint32_t a_khalf = (uint32_t)(lane & 16);
    const uint32_t b_lrow = (uint32_t)((lane & 7) | ((lane & 16) >> 1));
    const uint32_t b_khalf = (uint32_t)((lane & 8) << 1);

    for (int c = 0; c < NC; ++c) {
        if (c + P < NC) {
            load_chunk(c + P);
            asm volatile("cp.async.wait_group %0;" :: "n"(P) : "memory");
        } else {
            asm volatile("cp.async.wait_group 0;" ::: "memory");
        }
        __syncthreads();

        uint32_t st = sb + (uint32_t)((c % STAGES) * STAGE);
        #pragma unroll
        for (int ks = 0; ks < 4; ks++) {
            uint32_t a[2][MT][4], bf[NP][4];
            #pragma unroll
            for (int mi = 0; mi < MT; mi++) {
                uint32_t off = (uint32_t)((wm0 + mi * 16 + a_lrow) * 128) + (uint32_t)(ks * 32) + a_khalf;
                ldsm4(a[0][mi], st + (off ^ xorm));
                ldsm4(a[1][mi], st + ABYTES + (off ^ xorm));
            }
            #pragma unroll
            for (int pi = 0; pi < NP; pi++) {
                uint32_t off = (uint32_t)((wn0 + pi * 16 + b_lrow) * 128) + (uint32_t)(ks * 32) + b_khalf;
                ldsm4(bf[pi], st + 2 * ABYTES + (off ^ xorm));
            }
            #pragma unroll
            for (int mi = 0; mi < MT; mi++)
                #pragma unroll
                for (int pi = 0; pi < NP; pi++) {
                    mma16816(acc[mi][2 * pi],     a[0][mi], &bf[pi][0]);
                    mma16816(acc[mi][2 * pi + 1], a[0][mi], &bf[pi][2]);
                    mma16816(acc[mi][2 * pi],     a[1][mi], &bf[pi][0]);
                    mma16816(acc[mi][2 * pi + 1], a[1][mi], &bf[pi][2]);
                }
        }
        __syncthreads();
    }

    // epilogue
    int g4 = lane >> 2, t4 = lane & 3;
    #pragma unroll
    for (int mi = 0; mi < MT; mi++) {
        #pragma unroll
        for (int ni = 0; ni < 2 * NP; ni++) {
            int m = m0 + wm0 + mi * 16 + g4;
            int col = n0 + wn0 + ni * 8 + t4 * 2;
            float bx = bias[col], by = bias[col + 1];
            float v00 = acc[mi][ni][0] + bx, v01 = acc[mi][ni][1] + by;
            float v10 = acc[mi][ni][2] + bx, v11 = acc[mi][ni][3] + by;
            if (OUTM == 1) {
                __half h0, l0, h1, l1;
                long base0 = (long)b * strideC + (long)m * 256 + col;
                long base1 = (long)b * strideC + (long)(m + 8) * 256 + col;
                split2h(v00, h0, l0); split2h(v01, h1, l1);
                *(__half2*)&Chi[base0] = __halves2half2(h0, h1);
                *(__half2*)&Clo[base0] = __halves2half2(l0, l1);
                split2h(v10, h0, l0); split2h(v11, h1, l1);
                *(__half2*)&Chi[base1] = __halves2half2(h0, h1);
                *(__half2*)&Clo[base1] = __halves2half2(l0, l1);
            } else {
                int d0 = rowmap[b * 256 + m];
                int d1 = rowmap[b * 256 + m + 8];
                if (d0 >= 0)
                    *(float2*)&Cf[(long)b * strideC + (long)d0 * 256 + col] = make_float2(v00, v01);
                if (d1 >= 0)
                    *(float2*)&Cf[(long)b * strideC + (long)d1 * 256 + col] = make_float2(v10, v11);
            }
        }
    }
}

// ---------------- substitution gathers: pure half2 copies ----------------
__global__ void __launch_bounds__(1024) k_gather_x1() {
    int l = blockIdx.x * 8 + (threadIdx.x >> 7);
    int b = blockIdx.y;
    int d = (threadIdx.x & 127) * 2;
    int sr = g_srcrow1[b * L1C + l];
    long dst = ((long)b * L1C + l) * DC + d;
    long src = (sr >= 0) ? ((long)b * L1C + sr) * DC + d
                         : ((long)b * SC + L2C + l) * DC + d;
    const __half* hi = (sr >= 0) ? g_y0hi : g_Ehi;
    const __half* lo = (sr >= 0) ? g_y0lo : g_Elo;
    *(__half2*)&g_x1hi[dst] = *(const __half2*)&hi[src];
    *(__half2*)&g_x1lo[dst] = *(const __half2*)&lo[src];
}

__global__ void __launch_bounds__(1024) k_gather_x2() {
    int l = blockIdx.x * 8 + (threadIdx.x >> 7);
    int b = blockIdx.y;
    int d = (threadIdx.x & 127) * 2;
    int sr = g_srcrow2[b * L2C + l];
    long dst = ((long)b * L2C + l) * DC + d;
    long src = (sr >= 0) ? ((long)b * 1024 + sr) * DC + d
                         : ((long)b * SC + l) * DC + d;
    const __half* hi = (sr >= 0) ? g_y1hi : g_Ehi;
    const __half* lo = (sr >= 0) ? g_y1lo : g_Elo;
    *(__half2*)&g_x2hi[dst] = *(const __half2*)&hi[src];
    *(__half2*)&g_x2lo[dst] = *(const __half2*)&lo[src];
}

// ---------------- launch ----------------
extern "C" void kernel_launch(void* const* d_in, const int* in_sizes, int n_in,
                              void* d_out, int out_size) {
    (void)in_sizes; (void)n_in; (void)out_size;
    const int*   value    = (const int*)d_in[0];
    const int*   depth    = (const int*)d_in[1];
    const int*   position = (const int*)d_in[2];
    const float* emb_val  = (const float*)d_in[3];
    const float* emb_dep  = (const float*)d_in[4];
    const float* emb_pos  = (const float*)d_in[5];
    const float* W0 = (const float*)d_in[6];
    const float* b0 = (const float*)d_in[7];
    const float* W1 = (const float*)d_in[8];
    const float* b1 = (const float*)d_in[9];
    const float* W2 = (const float*)d_in[10];
    const float* b2 = (const float*)d_in[11];
    float* out = (float*)d_out;

    __half *w0, *w1, *w2, *ehi, *elo, *x1h, *x1l, *x2h, *x2l;
    __half *y0h, *y0l, *y1h, *y1l;
    int* odst;
    cudaGetSymbolAddress((void**)&w0, g_W0);
    cudaGetSymbolAddress((void**)&w1, g_W1);
    cudaGetSymbolAddress((void**)&w2, g_W2);
    cudaGetSymbolAddress((void**)&ehi, g_Ehi);  cudaGetSymbolAddress((void**)&elo, g_Elo);
    cudaGetSymbolAddress((void**)&x1h, g_x1hi); cudaGetSymbolAddress((void**)&x1l, g_x1lo);
    cudaGetSymbolAddress((void**)&x2h, g_x2hi); cudaGetSymbolAddress((void**)&x2l, g_x2lo);
    cudaGetSymbolAddress((void**)&y0h, g_y0hi); cudaGetSymbolAddress((void**)&y0l, g_y0lo);
    cudaGetSymbolAddress((void**)&y1h, g_y1hi); cudaGetSymbolAddress((void**)&y1l, g_y1lo);
    cudaGetSymbolAddress((void**)&odst, g_outdst);

    const int SMEM0 = 2 * (2 * 128 * 128 + 128 * 128);  // 98304 (BM128,BN128, 2 stages)
    const int SMEM1 = 4 * (2 * 64 * 128 + 64 * 128);    // 98304 (64x64, 4 stages)
    cudaFuncSetAttribute(k_gemm<128, 128, 2048, 2, 1>, cudaFuncAttributeMaxDynamicSharedMemorySize, SMEM0);
    cudaFuncSetAttribute(k_gemm<64, 64, 2048, 4, 1>,   cudaFuncAttributeMaxDynamicSharedMemorySize, SMEM1);
    cudaFuncSetAttribute(k_gemm<64, 64, 1024, 4, 2>,   cudaFuncAttributeMaxDynamicSharedMemorySize, SMEM1);

    // prep: indices + weight convert + zero-out + embedding, one launch
    k_prep<<<PREP_GRID, 1024>>>(value, depth, position, emb_val, emb_dep, emb_pos,
                                W0, W1, W2, out);

    // GEMM0: 8192 x 2048 x 256 per batch — 256 CTAs, 2 CTAs/SM, 1 wave
    k_gemm<128, 128, 2048, 2, 1><<<dim3(64, 2, BB), 256, SMEM0>>>(
        ehi + (long)(L2C + L1C) * DC, elo + (long)(L2C + L1C) * DC, (long)SC * DC,
        w0, b0, y0h, y0l, nullptr, nullptr, (long)L1C * DC);
    k_gather_x1<<<dim3(L1C / 8, BB), 1024>>>();
    // GEMM1: 1024 x 2048 x 256 per batch
    k_gemm<64, 64, 2048, 4, 1><<<dim3(16, 4, BB), 256, SMEM1>>>(
        x1h, x1l, (long)L1C * DC, w1, b1, y1h, y1l, nullptr, nullptr, (long)1024 * DC);
    k_gather_x2<<<dim3(L2C / 8, BB), 1024>>>();
    // GEMM2: 256 x 1024 x 256 per batch, scatter rows directly into out
    k_gemm<64, 64, 1024, 4, 2><<<dim3(4, 4, BB), 256, SMEM1>>>(
        x2h, x2l, (long)L2C * DC, w2, b2, nullptr, nullptr, out, odst, (long)(256 * 256));
}

// round 10
// speedup vs baseline: 2.3959x; 2.3959x over previous
#include <cuda_runtime.h>
#include <cuda_fp16.h>
#include <cstdint>

// ---------------- problem constants ----------------
#define BB   2
#define L2C  1024
#define L1C  8192
#define L0C  65536
#define SC   (L2C + L1C + L0C)   // 74752
#define DC   256
#define EN   131                 // P entries per tap: 32 (val,dep) combos + 3*33 pos

// ---------------- scratch (__device__ globals) ----------------
__device__ __half g_W1[256 * 2048];
__device__ __half g_W2[256 * 1024];
__device__ float  g_Wt0[8 * 256 * 256];        // W0 transposed: [t][d][o]
__device__ float  g_P[8 * EN * 256];           // precomputed conv0 tables [t][e][o]
__device__ __half g_x1hi[BB * L1C * DC], g_x1lo[BB * L1C * DC];
__device__ __half g_x2hi[BB * L2C * DC], g_x2lo[BB * L2C * DC];
__device__ float  g_part[4 * BB * 1024 * 256]; // GEMM1 split-K partials
__device__ int    g_inv1[BB * L1C];            // y0 src row -> x1 target (-1 none)
__device__ int    g_inv2[BB * L2C];            // y1 src row -> x2 target (-1 none)
__device__ int    g_outdst[BB * 256];          // conv2 row -> out slot (-1 none)

// ---------------- helpers ----------------
__device__ __forceinline__ uint32_t smem_u32(const void* p) {
    uint32_t a;
    asm("{ .reg .u64 t; cvta.to.shared.u64 t, %1; cvt.u32.u64 %0, t; }" : "=r"(a) : "l"(p));
    return a;
}
__device__ __forceinline__ void split2h(float x, __half& h, __half& l) {
    h = __float2half(x);
    l = __float2half(x - __half2float(h));
}
__device__ __forceinline__ void cpasync16(uint32_t saddr, const void* gaddr) {
    asm volatile("cp.async.cg.shared.global [%0], [%1], 16;" :: "r"(saddr), "l"(gaddr));
}
__device__ __forceinline__ void ldsm4(uint32_t* r, uint32_t a) {
    asm volatile("ldmatrix.sync.aligned.m8n8.x4.shared.b16 {%0,%1,%2,%3}, [%4];"
                 : "=r"(r[0]), "=r"(r[1]), "=r"(r[2]), "=r"(r[3]) : "r"(a));
}
__device__ __forceinline__ void mma16816(float* d, const uint32_t* a, const uint32_t* b) {
    asm volatile(
        "mma.sync.aligned.m16n8k16.row.col.f32.f16.f16.f32 "
        "{%0,%1,%2,%3}, {%4,%5,%6,%7}, {%8,%9}, {%0,%1,%2,%3};"
        : "+f"(d[0]), "+f"(d[1]), "+f"(d[2]), "+f"(d[3])
        : "r"(a[0]), "r"(a[1]), "r"(a[2]), "r"(a[3]), "r"(b[0]), "r"(b[1]));
}

__device__ __forceinline__ int exscan1024(int v, int tid, int* sW, int* total) {
    int lane = tid & 31, w = tid >> 5;
    int x = v;
    #pragma unroll
    for (int o = 1; o < 32; o <<= 1) {
        int t = __shfl_up_sync(0xFFFFFFFFu, x, o);
        if (lane >= o) x += t;
    }
    if (lane == 31) sW[w] = x;
    __syncthreads();
    if (tid < 32) {
        int y = sW[lane];
        #pragma unroll
        for (int o = 1; o < 32; o <<= 1) {
            int t = __shfl_up_sync(0xFFFFFFFFu, y, o);
            if (lane >= o) y += t;
        }
        sW[lane] = y;
    }
    __syncthreads();
    int off = (w == 0) ? 0 : sW[w - 1];
    int tot = sW[31];
    __syncthreads();
    *total = tot;
    return off + x - v;
}

// ---------------- prep1: indices | W0 transpose | embed L1/L2 | wsplit | zero ----------------
#define IDX_NB 6
#define TRN_B0 6
#define TRN_NB 32
#define EMB_B0 (TRN_B0 + TRN_NB)          // 38
#define EMB_NB 2304                        // 18432 rows / 8
#define WSP_B0 (EMB_B0 + EMB_NB)           // 2342
#define WSP_NB 768                         // 786432 / 1024
#define ZER_B0 (WSP_B0 + WSP_NB)           // 3110
#define ZER_NB 8
#define PREP_GRID (ZER_B0 + ZER_NB)        // 3118
#define PREP_SMEM 66048

__global__ void __launch_bounds__(1024) k_prep1(
    const int* __restrict__ value, const int* __restrict__ depth,
    const int* __restrict__ position,
    const float* __restrict__ emb_val, const float* __restrict__ emb_dep,
    const float* __restrict__ emb_pos,
    const float* __restrict__ W0, const float* __restrict__ W1,
    const float* __restrict__ W2, float* __restrict__ out)
{
    extern __shared__ char dsm[];
    int bid = blockIdx.x, tid = threadIdx.x;

    if (bid >= ZER_B0) {
        float4 z = make_float4(0.f, 0.f, 0.f, 0.f);
        for (int i = (bid - ZER_B0) * 1024 + tid; i < 32768; i += ZER_NB * 1024)
            ((float4*)out)[i] = z;
        return;
    }
    if (bid >= WSP_B0) {
        // weight fp16 convert: Wk[o][t*256+d] = fp16(W[o,d,t])
        int idx = (bid - WSP_B0) * 1024 + tid;
        const float* W; __half* O; int sK;
        if (idx < 524288)      { W = W1; O = g_W1; sK = 8; }
        else                   { idx -= 524288; W = W2; O = g_W2; sK = 4; }
        int d = idx & 255;
        int rem = idx >> 8;
        int t = rem % sK;
        int o = rem / sK;
        O[o * (sK * 256) + t * 256 + d] = __float2half(W[(o * 256 + d) * sK + t]);
        return;
    }
    if (bid >= EMB_B0) {
        // embedding for L2 + L1 rows only -> default x2 / x1 (hi/lo fp16)
        int r = (bid - EMB_B0) * 8 + (tid >> 7);
        if (r >= BB * (L2C + L1C)) return;
        int b = r / (L2C + L1C);
        int lr = r - b * (L2C + L1C);
        long tok = (long)b * SC + lr;
        int d = (tid & 127) * 2;
        int v = value[tok], dep = depth[tok];
        const int* p = position + tok * 3;
        float2 e = *(const float2*)&emb_val[v * DC + d];
        float2 t2;
        t2 = *(const float2*)&emb_dep[dep * DC + d];              e.x += t2.x; e.y += t2.y;
        t2 = *(const float2*)&emb_pos[(0 * 33 + p[0]) * DC + d];  e.x += t2.x; e.y += t2.y;
        t2 = *(const float2*)&emb_pos[(1 * 33 + p[1]) * DC + d];  e.x += t2.x; e.y += t2.y;
        t2 = *(const float2*)&emb_pos[(2 * 33 + p[2]) * DC + d];  e.x += t2.x; e.y += t2.y;
        __half h0, l0, h1, l1;
        split2h(e.x, h0, l0); split2h(e.y, h1, l1);
        long dst;
        __half *HI, *LO;
        if (lr < L2C) { dst = ((long)b * L2C + lr) * DC + d;          HI = g_x2hi; LO = g_x2lo; }
        else          { dst = ((long)b * L1C + (lr - L2C)) * DC + d;  HI = g_x1hi; LO = g_x1lo; }
        *(__half2*)&HI[dst] = __halves2half2(h0, h1);
        *(__half2*)&LO[dst] = __halves2half2(l0, l1);
        return;
    }
    if (bid >= TRN_B0) {
        // W0 transpose -> Wt0[t][d][o], smem-tiled (o-tile 64, d-tile 32)
        float* ts = (float*)dsm;    // [64][257]
        int blk = bid - TRN_B0;
        int o0 = (blk >> 3) * 64;
        int d0 = (blk & 7) * 32;
        for (int i = tid; i < 64 * 256; i += 1024) {
            int ol = i >> 8, j = i & 255;            // j = dl*8 + t
            ts[ol * 257 + j] = W0[(o0 + ol) * 2048 + d0 * 8 + j];
        }
        __syncthreads();
        for (int i = tid; i < 64 * 256; i += 1024) {
            int td = i >> 6, ol = i & 63;
            int dl = td >> 3, t = td & 7;
            g_Wt0[(t * 256 + d0 + dl) * 256 + o0 + ol] = ts[ol * 257 + dl * 8 + t];
        }
        return;
    }

    // ---- indices: 6 blocks (b, sec) ----
    int* sOrder = (int*)dsm;            // 8192 ints
    int* sScan  = sOrder + 8192;        // 32 ints
    int b = bid / 3;
    int sec = bid % 3;
    const int* vb = value + (long)b * SC;

    if (sec == 0) {
        // sub1: sources = v0 heads (8192), targets = v1==2 (8192); build inv1[src]=tgt
        for (int i = tid; i < L1C; i += 1024) g_inv1[b * L1C + i] = -1;
        int base = tid * 8, local = 0;
        unsigned mask = 0;
        #pragma unroll
        for (int i = 0; i < 8; i++) {
            int p = (vb[L2C + L1C + (base + i) * 8] != 0);
            mask |= (unsigned)p << i; local += p;
        }
        int tot; int ex = exscan1024(local, tid, sScan, &tot);
        int rt = ex, rf = base - ex;
        #pragma unroll
        for (int i = 0; i < 8; i++) {
            int j = base + i;
            if ((mask >> i) & 1u) sOrder[rt++] = j;
            else                  sOrder[tot + rf++] = j;
        }
        __syncthreads();
        local = 0; mask = 0;
        #pragma unroll
        for (int i = 0; i < 8; i++) {
            int p = (vb[L2C + base + i] == 2);
            mask |= (unsigned)p << i; local += p;
        }
        ex = exscan1024(local, tid, sScan, &tot);
        int r = ex;
        #pragma unroll
        for (int i = 0; i < 8; i++) {
            int j = base + i;
            if ((mask >> i) & 1u) { g_inv1[b * L1C + sOrder[min(r, 8191)]] = j; r++; }
        }
    } else if (sec == 1) {
        // sub2: sources = v1 heads (1024), targets = v2==2 (1024); inv2[src]=tgt
        g_inv2[b * L2C + tid] = -1;
        int p = (vb[L2C + tid * 8] != 0);
        int tot; int ex = exscan1024(p, tid, sScan, &tot);
        if (p) sOrder[ex] = tid;
        else   sOrder[tot + tid - ex] = tid;
        __syncthreads();
        int q = (vb[tid] == 2);
        int ex2 = exscan1024(q, tid, sScan, &tot);
        if (q) g_inv2[b * L2C + sOrder[min(ex2, 1023)]] = tid;
    } else {
        // output compaction map
        int any = 0;
        #pragma unroll
        for (int t = 0; t < 8; t++) any |= (vb[L2C + tid * 8 + t] == 2);
        sOrder[tid] = any;
        __syncthreads();
        int p = (vb[tid] == 2);
        int tot; int ex = exscan1024(p, tid, sScan, &tot);
        int m2 = p ? sOrder[min(ex, 1023)] : 0;
        sOrder[2048 + tid] = m2;
        __syncthreads();
        int m2g = 0;
        if (tid < 256)
            m2g = sOrder[2048 + 4 * tid] | sOrder[2048 + 4 * tid + 1]
                | sOrder[2048 + 4 * tid + 2] | sOrder[2048 + 4 * tid + 3];
        int tot2; int ex2 = exscan1024((tid < 256 && m2g) ? 1 : 0, tid, sScan, &tot2);
        if (tid < 256) g_outdst[b * 256 + tid] = m2g ? ex2 : -1;
    }
}

// ---------------- prep2: P[t][e][o] = sum_d Wt0[t][d][o] * c[e][d] ----------------
__global__ void __launch_bounds__(256) k_prep2(
    const float* __restrict__ emb_val, const float* __restrict__ emb_dep,
    const float* __restrict__ emb_pos)
{
    __shared__ float sc[8][256];
    int t = blockIdx.x / 17;
    int e0 = (blockIdx.x % 17) * 8;
    int tid = threadIdx.x;

    for (int i = tid; i < 8 * 256; i += 256) {
        int ee = i >> 8, d = i & 255;
        int e = e0 + ee;
        float cv = 0.f;
        if (e < EN) {
            if (e < 32) cv = emb_val[(e >> 3) * 256 + d] + emb_dep[(e & 7) * 256 + d];
            else        cv = emb_pos[(e - 32) * 256 + d];
        }
        sc[ee][d] = cv;
    }
    __syncthreads();

    float acc[8];
    #pragma unroll
    for (int ee = 0; ee < 8; ee++) acc[ee] = 0.f;
    const float* wt = g_Wt0 + (long)t * 256 * 256 + tid;
    for (int d = 0; d < 256; d++) {
        float wv = wt[d * 256];
        #pragma unroll
        for (int ee = 0; ee < 8; ee++) acc[ee] += wv * sc[ee][d];
    }
    #pragma unroll
    for (int ee = 0; ee < 8; ee++) {
        int e = e0 + ee;
        if (e < EN) g_P[((long)t * EN + e) * 256 + tid] = acc[ee];
    }
}

// ---------------- k_y0: fused conv0-from-tables, scattered into x1 ----------------
__global__ void __launch_bounds__(256) k_y0(
    const int* __restrict__ value, const int* __restrict__ depth,
    const int* __restrict__ position, const float* __restrict__ b0)
{
    int b = blockIdx.y;
    int half = threadIdx.x >> 7;
    int lane = threadIdx.x & 127;
    int col = lane * 2;
    float2 bias = *(const float2*)&b0[col];

    #pragma unroll
    for (int j = 0; j < 4; j++) {
        int s = blockIdx.x * 8 + half * 4 + j;            // source row in y0 (0..8191)
        int tgt = g_inv1[b * L1C + s];
        if (tgt < 0) continue;
        long tokbase = (long)b * SC + L2C + L1C + s * 8;
        float2 acc = bias;
        #pragma unroll
        for (int t = 0; t < 8; t++) {
            long tok = tokbase + t;
            int v = value[tok], dep = depth[tok];
            const int* p = position + tok * 3;
            const float* Pt = g_P + (long)t * EN * 256;
            float2 a0 = *(const float2*)&Pt[(((v << 3) | dep)) * 256 + col];
            float2 a1 = *(const float2*)&Pt[(32 + p[0]) * 256 + col];
            float2 a2 = *(const float2*)&Pt[(65 + p[1]) * 256 + col];
            float2 a3 = *(const float2*)&Pt[(98 + p[2]) * 256 + col];
            acc.x += a0.x + a1.x + a2.x + a3.x;
            acc.y += a0.y + a1.y + a2.y + a3.y;
        }
        __half h0, l0, h1, l1;
        split2h(acc.x, h0, l0); split2h(acc.y, h1, l1);
        long dst = ((long)b * L1C + tgt) * DC + col;
        *(__half2*)&g_x1hi[dst] = __halves2half2(h0, h1);
        *(__half2*)&g_x1lo[dst] = __halves2half2(l0, l1);
    }
}

// ---------------- 2-term fp16 split GEMM via mma.sync ----------------
// OUTM=2: fp32 scatter rows via rowmap (+bias). OUTM=3: split-K fp32 partials (no bias).
template <int BM, int BN, int KK, int LDK, int STAGES, int OUTM>
__global__ void __launch_bounds__(256, 2) k_gemm(
    const __half* __restrict__ Ahi, const __half* __restrict__ Alo, long strideA,
    const __half* __restrict__ Bh, const float* __restrict__ bias,
    float* __restrict__ Cf, const int* __restrict__ rowmap, long strideC)
{
    constexpr int NC = KK / 64;
    constexpr int P = STAGES - 1;
    constexpr int ABYTES = BM * 128;
    constexpr int BBYTES = BN * 128;
    constexpr int STAGE = 2 * ABYTES + BBYTES;
    constexpr int WM = BM / 2, WN = BN / 4;
    constexpr int MT = WM / 16, NP = WN / 16;
    constexpr int TOTROWS = 2 * BM + BN;

    extern __shared__ __align__(1024) char smem[];
    uint32_t sb = smem_u32(smem);

    int tid = threadIdx.x;
    int lane = tid & 31, wid = tid >> 5;
    int wm0 = (wid >> 2) * WM;
    int wn0 = (wid & 3) * WN;
    int m0 = blockIdx.x * BM;
    int b = blockIdx.z;
    int n0, koff;
    if (OUTM == 3) { n0 = 0; koff = blockIdx.y * KK; }
    else           { n0 = blockIdx.y * BN; koff = 0; }

    const __half* Ah = Ahi + (long)b * strideA;
    const __half* Al = Alo + (long)b * strideA;

    float acc[MT][2 * NP][4];
    #pragma unroll
    for (int i = 0; i < MT; i++)
        #pragma unroll
        for (int j = 0; j < 2 * NP; j++)
            #pragma unroll
            for (int k = 0; k < 4; k++) acc[i][j][k] = 0.f;

    auto load_chunk = [&](int c) {
        uint32_t st = sb + (uint32_t)((c % STAGES) * STAGE);
        long k0 = (long)koff + c * 64;
        #pragma unroll
        for (int i = tid; i < TOTROWS * 8; i += 256) {
            int r = i >> 3, seg = i & 7;
            const __half* g;
            uint32_t base;
            if (r < BM)          { g = Ah + (long)(m0 + r) * LDK;                  base = st; }
            else if (r < 2 * BM) { int rr = r - BM;     g = Al + (long)(m0 + rr) * LDK; base = st + ABYTES;     r = rr; }
            else                 { int rr = r - 2 * BM; g = Bh + (long)(n0 + rr) * LDK; base = st + 2 * ABYTES; r = rr; }
            uint32_t off = (uint32_t)(r * 128 + seg * 16);
            uint32_t dst = base + (off ^ (uint32_t)((r & 7) << 4));
            cpasync16(dst, g + k0 + seg * 8);
        }
        asm volatile("cp.async.commit_group;" ::: "memory");
    };

    #pragma unroll
    for (int pc = 0; pc < P && pc < NC; pc++) load_chunk(pc);

    const uint32_t xorm = (uint32_t)((lane & 7) << 4);
    const uint32_t a_lrow = (uint32_t)(lane & 15);
    const uint32_t a_khalf = (uint32_t)(lane & 16);
    const uint32_t b_lrow = (uint32_t)((lane & 7) | ((lane & 16) >> 1));
    const uint32_t b_khalf = (uint32_t)((lane & 8) << 1);

    for (int c = 0; c < NC; ++c) {
        if (c + P < NC) {
            load_chunk(c + P);
            asm volatile("cp.async.wait_group %0;" :: "n"(P) : "memory");
        } else {
            asm volatile("cp.async.wait_group 0;" ::: "memory");
        }
        __syncthreads();

        uint32_t st = sb + (uint32_t)((c % STAGES) * STAGE);
        #pragma unroll
        for (int ks = 0; ks < 4; ks++) {
            uint32_t a[2][MT][4], bf[NP][4];
            #pragma unroll
            for (int mi = 0; mi < MT; mi++) {
                uint32_t off = (uint32_t)((wm0 + mi * 16 + a_lrow) * 128) + (uint32_t)(ks * 32) + a_khalf;
                ldsm4(a[0][mi], st + (off ^ xorm));
                ldsm4(a[1][mi], st + ABYTES + (off ^ xorm));
            }
            #pragma unroll
            for (int pi = 0; pi < NP; pi++) {
                uint32_t off = (uint32_t)((wn0 + pi * 16 + b_lrow) * 128) + (uint32_t)(ks * 32) + b_khalf;
                ldsm4(bf[pi], st + 2 * ABYTES + (off ^ xorm));
            }
            #pragma unroll
            for (int mi = 0; mi < MT; mi++)
                #pragma unroll
                for (int pi = 0; pi < NP; pi++) {
                    mma16816(acc[mi][2 * pi],     a[0][mi], &bf[pi][0]);
                    mma16816(acc[mi][2 * pi + 1], a[0][mi], &bf[pi][2]);
                    mma16816(acc[mi][2 * pi],     a[1][mi], &bf[pi][0]);
                    mma16816(acc[mi][2 * pi + 1], a[1][mi], &bf[pi][2]);
                }
        }
        __syncthreads();
    }

    // epilogue
    int g4 = lane >> 2, t4 = lane & 3;
    #pragma unroll
    for (int mi = 0; mi < MT; mi++) {
        #pragma unroll
        for (int ni = 0; ni < 2 * NP; ni++) {
            int m = m0 + wm0 + mi * 16 + g4;
            int col = n0 + wn0 + ni * 8 + t4 * 2;
            if (OUTM == 3) {
                long base0 = (((long)blockIdx.y * BB + b) * 1024 + m) * 256 + col;
                *(float2*)&Cf[base0] = make_float2(acc[mi][ni][0], acc[mi][ni][1]);
                *(float2*)&Cf[base0 + 8 * 256] = make_float2(acc[mi][ni][2], acc[mi][ni][3]);
            } else {
                float bx = bias[col], by = bias[col + 1];
                int d0 = rowmap[b * 256 + m];
                int d1 = rowmap[b * 256 + m + 8];
                if (d0 >= 0)
                    *(float2*)&Cf[(long)b * strideC + (long)d0 * 256 + col] =
                        make_float2(acc[mi][ni][0] + bx, acc[mi][ni][1] + by);
                if (d1 >= 0)
                    *(float2*)&Cf[(long)b * strideC + (long)d1 * 256 + col] =
                        make_float2(acc[mi][ni][2] + bx, acc[mi][ni][3] + by);
            }
        }
    }
}

// ---------------- k_red1: reduce GEMM1 partials + bias, scatter into x2 ----------------
__global__ void __launch_bounds__(128) k_red1(const float* __restrict__ b1) {
    int row = blockIdx.x, b = blockIdx.y;
    int tgt = g_inv2[b * L2C + row];
    if (tgt < 0) return;
    int col = threadIdx.x * 2;
    float2 s = make_float2(b1[col], b1[col + 1]);
    #pragma unroll
    for (int sp = 0; sp < 4; sp++) {
        float2 v = *(const float2*)&g_part[(((long)sp * BB + b) * 1024 + row) * 256 + col];
        s.x += v.x; s.y += v.y;
    }
    __half h0, l0, h1, l1;
    split2h(s.x, h0, l0); split2h(s.y, h1, l1);
    long dst = ((long)b * L2C + tgt) * DC + col;
    *(__half2*)&g_x2hi[dst] = __halves2half2(h0, h1);
    *(__half2*)&g_x2lo[dst] = __halves2half2(l0, l1);
}

// ---------------- launch ----------------
extern "C" void kernel_launch(void* const* d_in, const int* in_sizes, int n_in,
                              void* d_out, int out_size) {
    (void)in_sizes; (void)n_in; (void)out_size;
    const int*   value    = (const int*)d_in[0];
    const int*   depth    = (const int*)d_in[1];
    const int*   position = (const int*)d_in[2];
    const float* emb_val  = (const float*)d_in[3];
    const float* emb_dep  = (const float*)d_in[4];
    const float* emb_pos  = (const float*)d_in[5];
    const float* W0 = (const float*)d_in[6];
    const float* b0 = (const float*)d_in[7];
    const float* W1 = (const float*)d_in[8];
    const float* b1 = (const float*)d_in[9];
    const float* W2 = (const float*)d_in[10];
    const float* b2 = (const float*)d_in[11];
    float* out = (float*)d_out;

    __half *w1, *w2, *x1h, *x1l, *x2h, *x2l;
    float *part;
    int *odst;
    cudaGetSymbolAddress((void**)&w1, g_W1);
    cudaGetSymbolAddress((void**)&w2, g_W2);
    cudaGetSymbolAddress((void**)&x1h, g_x1hi); cudaGetSymbolAddress((void**)&x1l, g_x1lo);
    cudaGetSymbolAddress((void**)&x2h, g_x2hi); cudaGetSymbolAddress((void**)&x2l, g_x2lo);
    cudaGetSymbolAddress((void**)&part, g_part);
    cudaGetSymbolAddress((void**)&odst, g_outdst);

    const int SMEM1 = 2 * ((2 * 64 + 256) * 128);   // 98304 (BM64,BN256, 2 stages)
    const int SMEM2 = 4 * ((2 * 64 + 64) * 128);    // 98304 (64x64, 4 stages)
    cudaFuncSetAttribute(k_prep1, cudaFuncAttributeMaxDynamicSharedMemorySize, PREP_SMEM);
    cudaFuncSetAttribute(k_gemm<64, 256, 512, 2048, 2, 3>, cudaFuncAttributeMaxDynamicSharedMemorySize, SMEM1);
    cudaFuncSetAttribute(k_gemm<64, 64, 1024, 1024, 4, 2>, cudaFuncAttributeMaxDynamicSharedMemorySize, SMEM2);

    // 1. prep1: indices + W0 transpose + embed(L1,L2) + W1/W2 fp16 + zero out
    k_prep1<<<PREP_GRID, 1024, PREP_SMEM>>>(value, depth, position,
                                            emb_val, emb_dep, emb_pos, W0, W1, W2, out);
    // 2. prep2: P tables (conv0 absorbed into embedding tables)
    k_prep2<<<8 * 17, 256>>>(emb_val, emb_dep, emb_pos);
    // 3. y0 via table gathers, scattered directly into x1
    k_y0<<<dim3(L1C / 8, BB), 256>>>(value, depth, position, b0);
    // 4. GEMM1: 1024 x 2048 x 256 per batch, split-K x4 -> partials
    k_gemm<64, 256, 512, 2048, 2, 3><<<dim3(16, 4, BB), 256, SMEM1>>>(
        x1h, x1l, (long)L1C * DC, w1, nullptr, part, nullptr, 0);
    // 5. reduce partials + b1, scatter into x2
    k_red1<<<dim3(1024, BB), 128>>>(b1);
    // 6. GEMM2: 256 x 1024 x 256 per batch, scatter rows into out
    k_gemm<64, 64, 1024, 1024, 4, 2><<<dim3(4, 4, BB), 256, SMEM2>>>(
        x2h, x2l, (long)L2C * DC, w2, b2, out, odst, (long)(256 * 256));
}